// round 7
// baseline (speedup 1.0000x reference)
#include <cuda_runtime.h>
#include <cstdint>
#define NN 20000
#define EE 320000
using u64 = unsigned long long;

__device__ float g_x[NN*3];
__device__ float g_h[NN*64];
__device__ float g_A[NN*64];
__device__ float g_B[NN*64];
__device__ float g_agg[NN*64];
__device__ float g_xacc[NN*3];
__device__ float g_cnt[NN];
__device__ float g_invc[NN];

__device__ __forceinline__ float silu(float v){ return __fdividef(v,1.f+__expf(-v)); }
__device__ __forceinline__ u64 mk2(float a,float b){u64 r;asm("mov.b64 %0,{%1,%2};":"=l"(r):"f"(a),"f"(b));return r;}
__device__ __forceinline__ u64 pk2(float a){u64 r;asm("mov.b64 %0,{%1,%1};":"=l"(r):"f"(a));return r;}
__device__ __forceinline__ u64 ffma2(u64 a,u64 b,u64 c){u64 d;asm("fma.rn.f32x2 %0,%1,%2,%3;":"=l"(d):"l"(a),"l"(b),"l"(c));return d;}
__device__ __forceinline__ float2 up2(u64 a){float x,y;asm("mov.b64 {%0,%1},%2;":"=f"(x),"=f"(y):"l"(a));return make_float2(x,y);}
__device__ __forceinline__ float fin(u64 a){float2 v=up2(a);return v.x+v.y;}

// ---- 16-edge warp matvec: lane owns cols (2l,2l+1); aT8[k][ep] packs edges (2ep,2ep+1)
__device__ __forceinline__ void mv16(const u64* __restrict__ aT8,const float* __restrict__ W,
                                     int lane,u64* aX,u64* aY){
#pragma unroll 8
  for(int k=0;k<64;k++){
    float2 w=*(const float2*)&W[k*64+lane*2];
    u64 wx=pk2(w.x),wy=pk2(w.y);
    const ulonglong2* ar=(const ulonglong2*)(aT8+k*8);
    ulonglong2 p0=ar[0],p1=ar[1],p2=ar[2],p3=ar[3];
    aX[0]=ffma2(p0.x,wx,aX[0]); aY[0]=ffma2(p0.x,wy,aY[0]);
    aX[1]=ffma2(p0.y,wx,aX[1]); aY[1]=ffma2(p0.y,wy,aY[1]);
    aX[2]=ffma2(p1.x,wx,aX[2]); aY[2]=ffma2(p1.x,wy,aY[2]);
    aX[3]=ffma2(p1.y,wx,aX[3]); aY[3]=ffma2(p1.y,wy,aY[3]);
    aX[4]=ffma2(p2.x,wx,aX[4]); aY[4]=ffma2(p2.x,wy,aY[4]);
    aX[5]=ffma2(p2.y,wx,aX[5]); aY[5]=ffma2(p2.y,wy,aY[5]);
    aX[6]=ffma2(p3.x,wx,aX[6]); aY[6]=ffma2(p3.x,wy,aY[6]);
    aX[7]=ffma2(p3.y,wx,aX[7]); aY[7]=ffma2(p3.y,wy,aY[7]);
  }
}

// ---- node-side scalar machinery (validated R4) ----
__device__ __forceinline__ void stageW(u64* dst,const float* __restrict__ src,int K,int tid,int nthr){
  int tot=(K/2)*64;
  for(int i=tid;i<tot;i+=nthr){
    int kp=i>>6,c=i&63;
    u64 v=mk2(src[(2*kp)*64+c],src[(2*kp+1)*64+c]);
    dst[(kp<<6)+((c&2)?32:0)+((c>>2)<<1)+(c&1)]=v;
  }
}
__device__ __forceinline__ void ainit(u64* acc,const float* b4,int q){
  float4 b=*(const float4*)&b4[q*4];
#pragma unroll
  for(int r=0;r<4;r++){
    acc[4*r]=mk2(b.x,0.f); acc[4*r+1]=mk2(b.y,0.f);
    acc[4*r+2]=mk2(b.z,0.f); acc[4*r+3]=mk2(b.w,0.f);
  }
}
__device__ __forceinline__ void a0init(u64* acc){
#pragma unroll
  for(int i=0;i<16;i++) acc[i]=0ull;
}
template<int K>
__device__ __forceinline__ void mv8p(const float* vb,int ST,const u64* Wp,int q,u64* acc){
#pragma unroll 8
  for(int kp=0;kp<K/2;kp+=2){
    ulonglong2 a0=*(const ulonglong2*)(vb+2*kp);
    ulonglong2 a1=*(const ulonglong2*)(vb+ST+2*kp);
    ulonglong2 a2=*(const ulonglong2*)(vb+2*ST+2*kp);
    ulonglong2 a3=*(const ulonglong2*)(vb+3*ST+2*kp);
    const u64* wr=Wp+(kp<<6)+2*q;
    ulonglong2 wa0=*(const ulonglong2*)wr;
    ulonglong2 wb0=*(const ulonglong2*)(wr+32);
    ulonglong2 wa1=*(const ulonglong2*)(wr+64);
    ulonglong2 wb1=*(const ulonglong2*)(wr+96);
#define RSTEP(r,A) \
    acc[4*r+0]=ffma2(A.x,wa0.x,acc[4*r+0]); acc[4*r+1]=ffma2(A.x,wa0.y,acc[4*r+1]); \
    acc[4*r+2]=ffma2(A.x,wb0.x,acc[4*r+2]); acc[4*r+3]=ffma2(A.x,wb0.y,acc[4*r+3]); \
    acc[4*r+0]=ffma2(A.y,wa1.x,acc[4*r+0]); acc[4*r+1]=ffma2(A.y,wa1.y,acc[4*r+1]); \
    acc[4*r+2]=ffma2(A.y,wb1.x,acc[4*r+2]); acc[4*r+3]=ffma2(A.y,wb1.y,acc[4*r+3]);
    RSTEP(0,a0) RSTEP(1,a1) RSTEP(2,a2) RSTEP(3,a3)
#undef RSTEP
  }
}

__global__ void k_zero(){
  int i=blockIdx.x*blockDim.x+threadIdx.x;
  if(i<NN) g_cnt[i]=0.f;
  if(i<NN*3) g_xacc[i]=0.f;
}
__global__ void k_count(const int* __restrict__ erow){
  int e=blockIdx.x*blockDim.x+threadIdx.x;
  if(e<EE) atomicAdd(&g_cnt[erow[e]],1.f);
}

// h0=h16@Wi+bi ; A=h0@EA+eb ; B=h0@EB ; init x, invc, agg=0  (validated R4)
__global__ void __launch_bounds__(256) k_embed(
    const float* __restrict__ h16,const float* __restrict__ xin,
    const float* __restrict__ Wi,const float* __restrict__ bi,
    const float* __restrict__ EA,const float* __restrict__ eb,
    const float* __restrict__ EB){
  extern __shared__ char sr[];
  u64* sWip=(u64*)sr; u64* sEAp=(u64*)(sr+4096); u64* sEBp=(u64*)(sr+20480);
  float* sbi=(float*)(sr+36864); float* seb=(float*)(sr+37120);
  float* vbase=(float*)(sr+37376);
  const int tid=threadIdx.x,wid=tid>>5,lane=tid&31,q=lane&15,g2=lane>>4;
  stageW(sWip,Wi,16,tid,256);
  stageW(sEAp,EA,64,tid,256);
  stageW(sEBp,EB,64,tid,256);
  if(tid<64){sbi[tid]=bi[tid];seb[tid]=eb[tid];}
  float* vb=vbase+wid*(8*84);
  int nbase=blockIdx.x*64+wid*8;
#pragma unroll
  for(int t=0;t<4;t++){
    int e=t*2+g2,n=nbase+e;
    if(q<4){
      float4 v=make_float4(0,0,0,0);
      if(n<NN) v=*(const float4*)&h16[n*16+q*4];
      *(float4*)&vb[e*84+q*4]=v;
    }
    if(n<NN) *(float4*)&g_agg[n*64+q*4]=make_float4(0,0,0,0);
  }
  if(lane<8){int n=nbase+lane; if(n<NN) g_invc[n]=__fdividef(1.f,fmaxf(g_cnt[n],1.f));}
  if(lane<24){int e=lane/3,d=lane-3*(lane/3),n=nbase+e; if(n<NN) g_x[n*3+d]=xin[n*3+d];}
  __syncthreads();
  u64 acc[16];
  ainit(acc,sbi,q);
  mv8p<16>(vb+g2*4*84,84,sWip,q,acc);
  __syncwarp();
#pragma unroll
  for(int r=0;r<4;r++){
    int e=g2*4+r,n=nbase+e;
    float4 h0=make_float4(fin(acc[4*r]),fin(acc[4*r+1]),fin(acc[4*r+2]),fin(acc[4*r+3]));
    *(float4*)&vb[e*84+16+q*4]=h0;
    if(n<NN) *(float4*)&g_h[n*64+q*4]=h0;
  }
  __syncwarp();
  ainit(acc,seb,q);
  mv8p<64>(vb+g2*4*84+16,84,sEAp,q,acc);
#pragma unroll
  for(int r=0;r<4;r++){
    int n=nbase+g2*4+r;
    if(n<NN) *(float4*)&g_A[n*64+q*4]=make_float4(fin(acc[4*r]),fin(acc[4*r+1]),fin(acc[4*r+2]),fin(acc[4*r+3]));
  }
  a0init(acc);
  mv8p<64>(vb+g2*4*84+16,84,sEBp,q,acc);
#pragma unroll
  for(int r=0;r<4;r++){
    int n=nbase+g2*4+r;
    if(n<NN) *(float4*)&g_B[n*64+q*4]=make_float4(fin(acc[4*r]),fin(acc[4*r+1]),fin(acc[4*r+2]),fin(acc[4*r+3]));
  }
}

// ---- edge kernel: 16 edges/warp, 128 edges/CTA ----
// smem: sW2 0(16K), sC1 16384(16K), w1c/b2/cb1/cw2 32768..33792,
// per-warp aT 33792+wid*4096 (4KB), per-warp meta 66560+wid*512 (512B)
__global__ void __launch_bounds__(256,3) k_edge(
    const int* __restrict__ erow,const int* __restrict__ ecol,
    const float* __restrict__ w1c,const float* __restrict__ W2,
    const float* __restrict__ b2,const float* __restrict__ CW1,
    const float* __restrict__ cb1,const float* __restrict__ cw2){
  extern __shared__ char sr[];
  float* sW2=(float*)sr; float* sC1=(float*)(sr+16384);
  float* sw1c=(float*)(sr+32768); float* sb2=(float*)(sr+33024);
  float* scb1=(float*)(sr+33280); float* scw2=(float*)(sr+33536);
  const int tid=threadIdx.x,wid=tid>>5,lane=tid&31;
  float* aT=(float*)(sr+33792+wid*4096);
  u64* aT8=(u64*)aT;
  float* meta=(float*)(sr+66560+wid*512);   // 128 floats/warp: uses 112
  float* dfb=meta; float* rad=meta+48; float* icb=meta+64;
  int* rw=(int*)(meta+80); int* cl=(int*)(meta+96);
  for(int i=tid;i<1024;i+=256){((float4*)sW2)[i]=((const float4*)W2)[i];((float4*)sC1)[i]=((const float4*)CW1)[i];}
  if(tid<64){sw1c[tid]=w1c[tid];sb2[tid]=b2[tid];scb1[tid]=cb1[tid];scw2[tid]=cw2[tid];}
  int ebase=blockIdx.x*128+wid*16;
  if(lane<16){
    int e=ebase+lane,r=erow[e],c=ecol[e];
    rw[lane]=r; cl[lane]=c;
    float dx=g_x[r*3]-g_x[c*3],dy=g_x[r*3+1]-g_x[c*3+1],dz=g_x[r*3+2]-g_x[c*3+2];
    dfb[lane*3]=dx; dfb[lane*3+1]=dy; dfb[lane*3+2]=dz;
    rad[lane]=dx*dx+dy*dy+dz*dz; icb[lane]=g_invc[r];
  }
  __syncthreads();
  // phase1: m1 = silu(A[r]+B[c]+rad*w1c) -> pair-transposed aT[k][ep]
  {
    int e=lane&15, half=lane>>4;
    int r=rw[e], c=cl[e];
    float rd=rad[e];
    const float4* ga=(const float4*)&g_A[r*64+half*32];
    const float4* gb=(const float4*)&g_B[c*64+half*32];
#pragma unroll
    for(int c4=0;c4<8;c4++){
      int col=half*32+c4*4;
      float4 a4=ga[c4],b4=gb[c4],w4=*(const float4*)&sw1c[col];
      aT[(col+0)*16+e]=silu(a4.x+b4.x+rd*w4.x);
      aT[(col+1)*16+e]=silu(a4.y+b4.y+rd*w4.y);
      aT[(col+2)*16+e]=silu(a4.z+b4.z+rd*w4.z);
      aT[(col+3)*16+e]=silu(a4.w+b4.w+rd*w4.w);
    }
  }
  __syncwarp();
  // matvec1: m = silu(m1 @ W2 + b2)
  u64 aX[8],aY[8];
  {
    float2 bb=*(const float2*)&sb2[lane*2];
    u64 bx=pk2(bb.x),by=pk2(bb.y);
#pragma unroll
    for(int i=0;i<8;i++){aX[i]=bx;aY[i]=by;}
  }
  mv16(aT8,sW2,lane,aX,aY);
  __syncwarp();                         // all lanes done reading aT
  // epilogue1: silu, red.v2 into agg, repack, store mT
#pragma unroll
  for(int ep=0;ep<8;ep++){
    float2 x=up2(aX[ep]), y=up2(aY[ep]);
    float mx0=silu(x.x),mx1=silu(x.y),my0=silu(y.x),my1=silu(y.y);
    float* a0=&g_agg[rw[2*ep]*64+lane*2];
    float* a1=&g_agg[rw[2*ep+1]*64+lane*2];
    asm volatile("red.global.add.v2.f32 [%0],{%1,%2};"::"l"(a0),"f"(mx0),"f"(my0):"memory");
    asm volatile("red.global.add.v2.f32 [%0],{%1,%2};"::"l"(a1),"f"(mx1),"f"(my1):"memory");
    aX[ep]=mk2(mx0,mx1); aY[ep]=mk2(my0,my1);
  }
#pragma unroll
  for(int i=0;i<8;i++){                 // staggered to spread banks
    int ep=(i+lane)&7;
    aT8[(2*lane)*8+ep]  =aX[ep];
    aT8[(2*lane+1)*8+ep]=aY[ep];
  }
  __syncwarp();
  // matvec2: t = m @ CW1 + cb1
  {
    float2 bb=*(const float2*)&scb1[lane*2];
    u64 bx=pk2(bb.x),by=pk2(bb.y);
#pragma unroll
    for(int i=0;i<8;i++){aX[i]=bx;aY[i]=by;}
  }
  mv16(aT8,sC1,lane,aX,aY);
  // epilogue2: phi_e = sum_c silu(t)*cw2
  {
    float2 cw=*(const float2*)&scw2[lane*2];
    u64 P[8];
#pragma unroll
    for(int ep=0;ep<8;ep++){
      float2 x=up2(aX[ep]), y=up2(aY[ep]);
      P[ep]=mk2(silu(x.x)*cw.x+silu(y.x)*cw.y, silu(x.y)*cw.x+silu(y.y)*cw.y);
    }
    u64 ONE=pk2(1.f);
#pragma unroll
    for(int off=1;off<32;off<<=1){
#pragma unroll
      for(int ep=0;ep<8;ep++){
        u64 o=__shfl_xor_sync(0xffffffffu,P[ep],off);
        P[ep]=ffma2(o,ONE,P[ep]);
      }
    }
    if(lane<16){
      float2 pp=up2(P[lane>>1]);
      float phi=(lane&1)?pp.y:pp.x;
      int r=rw[lane]; float s=phi*icb[lane];
      atomicAdd(&g_xacc[r*3+0],dfb[lane*3+0]*s);
      atomicAdd(&g_xacc[r*3+1],dfb[lane*3+1]*s);
      atomicAdd(&g_xacc[r*3+2],dfb[lane*3+2]*s);
    }
  }
}

// node: x+=xacc; t=silu([h|agg]@NW1+nb1); h+=t@NW2+nb2; next-layer A/B or final out (validated R4)
__global__ void __launch_bounds__(256) k_node(
    const float* __restrict__ NW1,const float* __restrict__ nb1,
    const float* __restrict__ NW2,const float* __restrict__ nb2,
    const float* __restrict__ WA,const float* __restrict__ ba,
    const float* __restrict__ WB,int last,float* __restrict__ outp){
  extern __shared__ char sr[];
  u64* sN1p=(u64*)sr;
  u64* sN2p=(u64*)(sr+32768);
  u64* sAp =(u64*)(sr+49152);
  float* snb1=(float*)(sr+65536); float* snb2=(float*)(sr+65792);
  float* sba=(float*)(sr+66048);
  float* vbase=(float*)(sr+66304);
  const int tid=threadIdx.x,wid=tid>>5,lane=tid&31,q=lane&15,g2=lane>>4;
  stageW(sN1p,NW1,128,tid,256);
  stageW(sN2p,NW2,64,tid,256);
  stageW(sAp,WA,64,tid,256);
  if(tid<64){snb1[tid]=nb1[tid];snb2[tid]=nb2[tid];sba[tid]=ba[tid];}
  float* vb=vbase+wid*1056;
  int nbase=blockIdx.x*64+wid*8;
#pragma unroll
  for(int t=0;t<4;t++){
    int e=t*2+g2,n=nbase+e;
    float4 h4=make_float4(0,0,0,0),a4=make_float4(0,0,0,0);
    if(n<NN){
      h4=*(const float4*)&g_h[n*64+q*4];
      a4=*(const float4*)&g_agg[n*64+q*4];
      *(float4*)&g_agg[n*64+q*4]=make_float4(0,0,0,0);
    }
    *(float4*)&vb[e*132+q*4]=h4;
    *(float4*)&vb[e*132+64+q*4]=a4;
  }
  if(lane<24){
    int e=lane/3,d=lane-3*(lane/3),n=nbase+e;
    if(n<NN){
      float nx=g_x[n*3+d]+g_xacc[n*3+d];
      g_x[n*3+d]=nx; g_xacc[n*3+d]=0.f;
      if(last) outp[NN*64+n*3+d]=nx;
    }
  }
  __syncthreads();
  u64 acc[16];
  ainit(acc,snb1,q);
  mv8p<128>(vb+g2*4*132,132,sN1p,q,acc);
  __syncwarp();
#pragma unroll
  for(int r=0;r<4;r++){
    int e=g2*4+r;
    *(float4*)&vb[e*132+64+q*4]=make_float4(
      silu(fin(acc[4*r])),silu(fin(acc[4*r+1])),silu(fin(acc[4*r+2])),silu(fin(acc[4*r+3])));
  }
  __syncthreads();
  if(!last) stageW(sN1p,WB,64,tid,256);
  ainit(acc,snb2,q);
  mv8p<64>(vb+g2*4*132+64,132,sN2p,q,acc);
  __syncwarp();
#pragma unroll
  for(int r=0;r<4;r++){
    int e=g2*4+r,n=nbase+e;
    float4 ho=*(const float4*)&vb[e*132+q*4];
    float4 hn=make_float4(ho.x+fin(acc[4*r]),ho.y+fin(acc[4*r+1]),
                          ho.z+fin(acc[4*r+2]),ho.w+fin(acc[4*r+3]));
    *(float4*)&vb[e*132+q*4]=hn;
    if(n<NN) *(float4*)&g_h[n*64+q*4]=hn;
  }
  __syncthreads();
  ainit(acc,sba,q);
  mv8p<64>(vb+g2*4*132,132,sAp,q,acc);
  if(last){
#pragma unroll
    for(int r=0;r<4;r++){
      int n=nbase+g2*4+r;
      if(n<NN) *(float4*)&outp[n*64+q*4]=make_float4(fin(acc[4*r]),fin(acc[4*r+1]),fin(acc[4*r+2]),fin(acc[4*r+3]));
    }
  } else {
#pragma unroll
    for(int r=0;r<4;r++){
      int n=nbase+g2*4+r;
      if(n<NN) *(float4*)&g_A[n*64+q*4]=make_float4(fin(acc[4*r]),fin(acc[4*r+1]),fin(acc[4*r+2]),fin(acc[4*r+3]));
    }
    a0init(acc);
    mv8p<64>(vb+g2*4*132,132,sN1p,q,acc);
#pragma unroll
    for(int r=0;r<4;r++){
      int n=nbase+g2*4+r;
      if(n<NN) *(float4*)&g_B[n*64+q*4]=make_float4(fin(acc[4*r]),fin(acc[4*r+1]),fin(acc[4*r+2]),fin(acc[4*r+3]));
    }
  }
}

extern "C" void kernel_launch(void* const* d_in,const int* in_sizes,int n_in,
                              void* d_out,int out_size){
  const float* h16=(const float*)d_in[0];
  const float* xin=(const float*)d_in[1];
  const int*   ei =(const int*  )d_in[2];
  const float* Wi =(const float*)d_in[3];
  const float* bi =(const float*)d_in[4];
  const float* ew1=(const float*)d_in[5];
  const float* eb1=(const float*)d_in[6];
  const float* ew2=(const float*)d_in[7];
  const float* eb2=(const float*)d_in[8];
  const float* cw1=(const float*)d_in[9];
  const float* cb1=(const float*)d_in[10];
  const float* cw2=(const float*)d_in[11];
  const float* nw1=(const float*)d_in[12];
  const float* nb1=(const float*)d_in[13];
  const float* nw2=(const float*)d_in[14];
  const float* nb2=(const float*)d_in[15];
  const float* Wo =(const float*)d_in[16];
  const float* bo =(const float*)d_in[17];
  float* outp=(float*)d_out;
  const int* erow=ei; const int* ecol=ei+EE;

  const int SME=58880, SMEDGE=70656, SMN=100096;
  cudaFuncSetAttribute(k_embed,cudaFuncAttributeMaxDynamicSharedMemorySize,SME);
  cudaFuncSetAttribute(k_edge, cudaFuncAttributeMaxDynamicSharedMemorySize,SMEDGE);
  cudaFuncSetAttribute(k_node, cudaFuncAttributeMaxDynamicSharedMemorySize,SMN);

  const int NB=(NN+63)/64;
  k_zero<<<(NN*3+255)/256,256>>>();
  k_count<<<(EE+255)/256,256>>>(erow);
  k_embed<<<NB,256,SME>>>(h16,xin,Wi,bi,ew1,eb1,ew1+64*64);
  for(int l=0;l<4;l++){
    k_edge<<<EE/128,256,SMEDGE>>>(erow,ecol,ew1+l*129*64+128*64,ew2+l*4096,eb2+l*64,
                                  cw1+l*4096,cb1+l*64,cw2+l*64);
    int last=(l==3);
    const float* WA = last ? Wo : ew1+(l+1)*129*64;
    const float* ba = last ? bo : eb1+(l+1)*64;
    const float* WB = last ? Wo : WA+64*64;
    k_node<<<NB,256,SMN>>>(nw1+l*128*64,nb1+l*64,nw2+l*4096,nb2+l*64,WA,ba,WB,last,outp);
  }
}